// round 3
// baseline (speedup 1.0000x reference)
#include <cuda_runtime.h>
#include <cuda_bf16.h>
#include <cstdint>

#define TOKENS 16384
#define HDIM   1024
#define FDIM   4096
#define WSZ    (FDIM*HDIM)

// ---------------- scratch (static device, no allocations) ----------------
__device__ int8_t g_xq  [(size_t)TOKENS*HDIM];   // 16 MB quantized rmsnorm(x)
__device__ int8_t g_wupq[WSZ];                   //  4 MB ternary w_up
__device__ int8_t g_wdnq[WSZ];                   //  4 MB ternary w_down
__device__ int8_t g_h2q [(size_t)TOKENS*FDIM];   // 64 MB quantized relu^2
__device__ int    g_up  [(size_t)TOKENS*FDIM];   // 256 MB GEMM1 result (exact ints)
__device__ float  g_mul1[TOKENS];
__device__ int    g_rowmax[TOKENS];              // relu-max of up (s32, >=0)
__device__ float  g_part[2048];
__device__ float  g_mw[2];                       // clip(mean|w_up|), clip(mean|w_dn|)

// ---------------- helpers ----------------
__device__ __forceinline__ uint32_t smem_u32(const void* p) {
    uint32_t a;
    asm("{ .reg .u64 t; cvta.to.shared.u64 t, %1; cvt.u32.u64 %0, t; }" : "=r"(a) : "l"(p));
    return a;
}
__device__ __forceinline__ void cp_async16(uint32_t smem, const void* gmem) {
    asm volatile("cp.async.cg.shared.global [%0], [%1], 16;" :: "r"(smem), "l"(gmem));
}
__device__ __forceinline__ void mma_s8(int* c, const uint32_t* a, const uint32_t* b) {
    asm volatile(
        "mma.sync.aligned.m16n8k32.row.col.s32.s8.s8.s32 "
        "{%0,%1,%2,%3}, {%4,%5,%6,%7}, {%8,%9}, {%0,%1,%2,%3};"
        : "+r"(c[0]), "+r"(c[1]), "+r"(c[2]), "+r"(c[3])
        : "r"(a[0]), "r"(a[1]), "r"(a[2]), "r"(a[3]), "r"(b[0]), "r"(b[1]));
}

// ---------------- elementwise kernels ----------------

// blocks 0..1023 -> |w_up|, 1024..2047 -> |w_dn|; deterministic partials
__global__ void k_reduce_abs(const float* __restrict__ wup, const float* __restrict__ wdn) {
    __shared__ float sh[256];
    int b = blockIdx.x;
    const float4* p = (const float4*)((b < 1024) ? wup : wdn);
    int bb = b & 1023;
    float s = 0.f;
    int base = bb * 1024 + threadIdx.x;
#pragma unroll
    for (int i = 0; i < 4; i++) {
        float4 v = p[base + i * 256];
        s += fabsf(v.x) + fabsf(v.y) + fabsf(v.z) + fabsf(v.w);
    }
    sh[threadIdx.x] = s; __syncthreads();
    for (int o = 128; o > 0; o >>= 1) {
        if (threadIdx.x < o) sh[threadIdx.x] += sh[threadIdx.x + o];
        __syncthreads();
    }
    if (threadIdx.x == 0) g_part[b] = sh[0];
}

__global__ void k_finalize_mw() {
    __shared__ float sh[256];
    for (int half = 0; half < 2; half++) {
        float s = 0.f;
        for (int i = threadIdx.x; i < 1024; i += 256) s += g_part[half * 1024 + i];
        sh[threadIdx.x] = s; __syncthreads();
        for (int o = 128; o > 0; o >>= 1) {
            if (threadIdx.x < o) sh[threadIdx.x] += sh[threadIdx.x + o];
            __syncthreads();
        }
        if (threadIdx.x == 0) g_mw[half] = fmaxf(sh[0] / (float)WSZ, 1e-5f);
        __syncthreads();
    }
}

__global__ void k_ternarize(const float* __restrict__ w, int which) {
    int8_t* out = which ? g_wdnq : g_wupq;
    float s = 1.0f / g_mw[which];
    size_t i = (size_t)blockIdx.x * blockDim.x + threadIdx.x;   // float4 index
    float4 v = ((const float4*)w)[i];
    int q0 = (int)rintf(fminf(fmaxf(v.x * s, -1.f), 1.f));
    int q1 = (int)rintf(fminf(fmaxf(v.y * s, -1.f), 1.f));
    int q2 = (int)rintf(fminf(fmaxf(v.z * s, -1.f), 1.f));
    int q3 = (int)rintf(fminf(fmaxf(v.w * s, -1.f), 1.f));
    uint32_t pk = (uint32_t)(q0 & 0xFF) | ((uint32_t)(q1 & 0xFF) << 8) |
                  ((uint32_t)(q2 & 0xFF) << 16) | ((uint32_t)(q3 & 0xFF) << 24);
    ((uint32_t*)out)[i] = pk;
}

// one block per token: rmsnorm -> absmax -> int8 quantize + mul1 + rowmax=0
__global__ void k_rmsnorm_quant(const float* __restrict__ x, const float* __restrict__ nw) {
    __shared__ float sh[256];
    __shared__ float s_inv, s_scale;
    int t = blockIdx.x, tid = threadIdx.x;
    float4 v = ((const float4*)(x + (size_t)t * HDIM))[tid];
    float4 w = ((const float4*)nw)[tid];
    float ss = v.x * v.x + v.y * v.y + v.z * v.z + v.w * v.w;
    sh[tid] = ss; __syncthreads();
    for (int o = 128; o > 0; o >>= 1) { if (tid < o) sh[tid] += sh[tid + o]; __syncthreads(); }
    if (tid == 0) s_inv = 1.0f / sqrtf(sh[0] * (1.0f / HDIM) + 1e-6f);
    __syncthreads();
    float inv = s_inv;
    float h0 = v.x * inv * w.x, h1 = v.y * inv * w.y, h2 = v.z * inv * w.z, h3 = v.w * inv * w.w;
    float m = fmaxf(fmaxf(fabsf(h0), fabsf(h1)), fmaxf(fabsf(h2), fabsf(h3)));
    sh[tid] = m; __syncthreads();
    for (int o = 128; o > 0; o >>= 1) { if (tid < o) sh[tid] = fmaxf(sh[tid], sh[tid + o]); __syncthreads(); }
    if (tid == 0) {
        float cm = fmaxf(sh[0], 1e-5f);
        s_scale = 127.0f / cm;
        g_mul1[t] = (cm / 127.0f) * g_mw[0];
        g_rowmax[t] = 0;
    }
    __syncthreads();
    float sc = s_scale;
    int q0 = (int)rintf(fminf(fmaxf(h0 * sc, -128.f), 127.f));
    int q1 = (int)rintf(fminf(fmaxf(h1 * sc, -128.f), 127.f));
    int q2 = (int)rintf(fminf(fmaxf(h2 * sc, -128.f), 127.f));
    int q3 = (int)rintf(fminf(fmaxf(h3 * sc, -128.f), 127.f));
    uint32_t pk = (uint32_t)(q0 & 0xFF) | ((uint32_t)(q1 & 0xFF) << 8) |
                  ((uint32_t)(q2 & 0xFF) << 16) | ((uint32_t)(q3 & 0xFF) << 24);
    ((uint32_t*)(g_xq + (size_t)t * HDIM))[tid] = pk;
}

// relu^2 + per-token absmax int8 quant
__global__ void k_relu2_quant() {
    size_t i = (size_t)blockIdx.x * 256 + threadIdx.x;    // int4 index over TOKENS*FDIM/4
    int t = (int)(i >> 10);                               // 1024 int4 per token row
    float mul1 = g_mul1[t];
    float rm = (float)g_rowmax[t] * mul1;
    float sc2 = 127.0f / fmaxf(rm * rm, 1e-5f);
    int4 u = ((const int4*)g_up)[i];
    float a0 = fmaxf((float)u.x, 0.f) * mul1, a1 = fmaxf((float)u.y, 0.f) * mul1;
    float a2 = fmaxf((float)u.z, 0.f) * mul1, a3 = fmaxf((float)u.w, 0.f) * mul1;
    int q0 = (int)rintf(fminf(a0 * a0 * sc2, 127.f));
    int q1 = (int)rintf(fminf(a1 * a1 * sc2, 127.f));
    int q2 = (int)rintf(fminf(a2 * a2 * sc2, 127.f));
    int q3 = (int)rintf(fminf(a3 * a3 * sc2, 127.f));
    uint32_t pk = (uint32_t)(q0 & 0xFF) | ((uint32_t)(q1 & 0xFF) << 8) |
                  ((uint32_t)(q2 & 0xFF) << 16) | ((uint32_t)(q3 & 0xFF) << 24);
    ((uint32_t*)g_h2q)[i] = pk;
}

// ---------------- int8 mma.sync GEMM ----------------
// C[m,n] = sum_k A[m0+m,k]*B[n0+n,k]; A,B int8 K-contiguous.
// Tile 128x128x64; 8 warps = 2(M) x 4(N); warp tile 64x32.
// SMEM rows padded to 80 B -> fragment loads are bank-conflict-free.
// EPI==1: store s32 to g_up + fused per-row relu-max.
// EPI==2: out = C*mul2[m] + resid (float).

#define TILE_B 10240   /* 128 rows * 80 B */

template <int KTOT, int EPI>
__global__ void __launch_bounds__(256)
k_gemm(const float* __restrict__ resid, float* __restrict__ out2) {
    __shared__ __align__(16) int8_t sm[2][2][TILE_B];
    __shared__ int s_rowmax[128];

    const int8_t* A = (EPI == 1) ? g_xq   : g_h2q;
    const int8_t* B = (EPI == 1) ? g_wupq : g_wdnq;
    const int KIT = KTOT / 64;

    int tid = threadIdx.x, wid = tid >> 5, lane = tid & 31;
    int wm = wid & 1, wn = wid >> 1;
    int m0 = blockIdx.y * 128, n0 = blockIdx.x * 128;
    int tg = lane & 3, gp = lane >> 2;

    if (EPI == 1 && tid < 128) s_rowmax[tid] = 0;

    // granule decomposition for loads: 512 granules of 16B per tile, 2 per thread
    int gr0 = tid, gr1 = tid + 256;
    int r0g = gr0 >> 2, c0g = gr0 & 3;
    int r1g = gr1 >> 2, c1g = gr1 & 3;

    auto load_stage = [&](int stage, int kit) {
        int k0 = kit * 64;
        uint32_t dA = smem_u32(sm[stage][0]);
        uint32_t dB = smem_u32(sm[stage][1]);
        cp_async16(dA + r0g * 80 + c0g * 16, A + (size_t)(m0 + r0g) * KTOT + k0 + c0g * 16);
        cp_async16(dA + r1g * 80 + c1g * 16, A + (size_t)(m0 + r1g) * KTOT + k0 + c1g * 16);
        cp_async16(dB + r0g * 80 + c0g * 16, B + (size_t)(n0 + r0g) * KTOT + k0 + c0g * 16);
        cp_async16(dB + r1g * 80 + c1g * 16, B + (size_t)(n0 + r1g) * KTOT + k0 + c1g * 16);
        asm volatile("cp.async.commit_group;" ::: "memory");
    };

    int acc[4][4][4];
#pragma unroll
    for (int i = 0; i < 4; i++)
#pragma unroll
        for (int j = 0; j < 4; j++)
#pragma unroll
            for (int r = 0; r < 4; r++) acc[i][j][r] = 0;

    load_stage(0, 0);

    for (int it = 0; it < KIT; it++) {
        int cur = it & 1;
        if (it + 1 < KIT) {
            load_stage(cur ^ 1, it + 1);
            asm volatile("cp.async.wait_group 1;" ::: "memory");
        } else {
            asm volatile("cp.async.wait_group 0;" ::: "memory");
        }
        __syncthreads();

        const int8_t* sA = sm[cur][0];
        const int8_t* sB = sm[cur][1];
#pragma unroll
        for (int ks = 0; ks < 2; ks++) {
            int kk = ks * 32 + tg * 4;
            uint32_t a[4][4], b[4][2];
#pragma unroll
            for (int mt = 0; mt < 4; mt++) {
                int row = wm * 64 + mt * 16 + gp;
                a[mt][0] = *(const uint32_t*)(sA + row * 80 + kk);
                a[mt][1] = *(const uint32_t*)(sA + (row + 8) * 80 + kk);
                a[mt][2] = *(const uint32_t*)(sA + row * 80 + kk + 16);
                a[mt][3] = *(const uint32_t*)(sA + (row + 8) * 80 + kk + 16);
            }
#pragma unroll
            for (int nt = 0; nt < 4; nt++) {
                int nr = wn * 32 + nt * 8 + gp;
                b[nt][0] = *(const uint32_t*)(sB + nr * 80 + kk);
                b[nt][1] = *(const uint32_t*)(sB + nr * 80 + kk + 16);
            }
#pragma unroll
            for (int mt = 0; mt < 4; mt++)
#pragma unroll
                for (int nt = 0; nt < 4; nt++)
                    mma_s8(acc[mt][nt], a[mt], b[nt]);
        }
        __syncthreads();
    }

    // ---------------- epilogue ----------------
    if (EPI == 1) {
#pragma unroll
        for (int mt = 0; mt < 4; mt++) {
            int lr0 = wm * 64 + mt * 16 + gp;       // local row of acc pair 0
            int mx0 = 0, mx1 = 0;
#pragma unroll
            for (int nt = 0; nt < 4; nt++) {
                int col = n0 + wn * 32 + nt * 8 + tg * 2;
                int* d0 = g_up + (size_t)(m0 + lr0) * FDIM + col;
                int* d1 = g_up + (size_t)(m0 + lr0 + 8) * FDIM + col;
                *(int2*)d0 = make_int2(acc[mt][nt][0], acc[mt][nt][1]);
                *(int2*)d1 = make_int2(acc[mt][nt][2], acc[mt][nt][3]);
                mx0 = max(mx0, max(acc[mt][nt][0], acc[mt][nt][1]));
                mx1 = max(mx1, max(acc[mt][nt][2], acc[mt][nt][3]));
            }
            // reduce across the quad (lanes sharing a row)
            mx0 = max(mx0, __shfl_xor_sync(0xFFFFFFFFu, mx0, 1));
            mx0 = max(mx0, __shfl_xor_sync(0xFFFFFFFFu, mx0, 2));
            mx1 = max(mx1, __shfl_xor_sync(0xFFFFFFFFu, mx1, 1));
            mx1 = max(mx1, __shfl_xor_sync(0xFFFFFFFFu, mx1, 2));
            if (tg == 0) {
                atomicMax(&s_rowmax[lr0], mx0);
                atomicMax(&s_rowmax[lr0 + 8], mx1);
            }
        }
        __syncthreads();
        if (tid < 128) atomicMax(&g_rowmax[m0 + tid], s_rowmax[tid]);
    } else {
#pragma unroll
        for (int mt = 0; mt < 4; mt++) {
            int r0 = m0 + wm * 64 + mt * 16 + gp;
            int r1 = r0 + 8;
            float m1a = g_mul1[r0], m1b = g_mul1[r1];
            float rma = (float)g_rowmax[r0] * m1a, rmb = (float)g_rowmax[r1] * m1b;
            float mul2a = (fmaxf(rma * rma, 1e-5f) / 127.0f) * g_mw[1];
            float mul2b = (fmaxf(rmb * rmb, 1e-5f) / 127.0f) * g_mw[1];
#pragma unroll
            for (int nt = 0; nt < 4; nt++) {
                int col = n0 + wn * 32 + nt * 8 + tg * 2;
                const float2 ra = *(const float2*)(resid + (size_t)r0 * HDIM + col);
                const float2 rb = *(const float2*)(resid + (size_t)r1 * HDIM + col);
                float2 oa, ob;
                oa.x = (float)acc[mt][nt][0] * mul2a + ra.x;
                oa.y = (float)acc[mt][nt][1] * mul2a + ra.y;
                ob.x = (float)acc[mt][nt][2] * mul2b + rb.x;
                ob.y = (float)acc[mt][nt][3] * mul2b + rb.y;
                *(float2*)(out2 + (size_t)r0 * HDIM + col) = oa;
                *(float2*)(out2 + (size_t)r1 * HDIM + col) = ob;
            }
        }
    }
}

// ---------------- launch ----------------
extern "C" void kernel_launch(void* const* d_in, const int* in_sizes, int n_in,
                              void* d_out, int out_size) {
    const float* x   = (const float*)d_in[0];
    const float* nw  = (const float*)d_in[1];
    const float* wup = (const float*)d_in[2];
    const float* wdn = (const float*)d_in[3];
    float* out = (float*)d_out;

    k_reduce_abs<<<2048, 256>>>(wup, wdn);
    k_finalize_mw<<<1, 256>>>();
    k_ternarize<<<WSZ / 4 / 256, 256>>>(wup, 0);
    k_ternarize<<<WSZ / 4 / 256, 256>>>(wdn, 1);
    k_rmsnorm_quant<<<TOKENS, 256>>>(x, nw);
    k_gemm<1024, 1><<<dim3(FDIM / 128, TOKENS / 128), 256>>>(nullptr, nullptr);
    k_relu2_quant<<<(int)((size_t)TOKENS * FDIM / 4 / 256), 256>>>();
    k_gemm<4096, 2><<<dim3(HDIM / 128, TOKENS / 128), 256>>>(x, out);
}